// round 2
// baseline (speedup 1.0000x reference)
#include <cuda_runtime.h>
#include <cstdint>

// Problem constants (fixed by the reference)
#define BB   32
#define CC   128
#define HH   128
#define WW   128
#define OH   64
#define OW   64
// output plane stride (vals / pos_h / pos_w planes)
#define PLANE ((size_t)CC * OH * OW)   // 524288

__device__ __forceinline__ void win2x2(float a, float b, float c, float d,
                                       int row0, int col0,
                                       float& val, float& ph, float& pw) {
    // first-max argmax over order [a, b, c, d] == flat idx kh*2+kw
    float best = a; int idx = 0;
    if (b > best) { best = b; idx = 1; }
    if (c > best) { best = c; idx = 2; }
    if (d > best) { best = d; idx = 3; }
    int row = row0 + (idx >> 1);
    int col = col0 + (idx & 1);
    val = best;
    ph = (float)row * (1.0f / (float)HH);
    pw = (float)col * (1.0f / (float)WW);
}

__global__ void __launch_bounds__(256)
pap_pool_kernel(const float* __restrict__ x, float* __restrict__ out) {
    // thread -> (bc, oh, ow4): ow4 indexes a QUAD of output columns
    // total threads = B*C*OH*(OW/4) = 32*128*64*16 = 4,194,304
    unsigned tid = blockIdx.x * blockDim.x + threadIdx.x;

    unsigned ow4 = tid & 15u;          // OW/4 = 16 quads
    unsigned oh  = (tid >> 4) & 63u;   // OH = 64
    unsigned bc  = tid >> 10;          // b*C + c, 0..4095

    // input: rows (2*oh, 2*oh+1), cols [8*ow4, 8*ow4+8) -> 4 float4 streaming loads
    const float4* xr = reinterpret_cast<const float4*>(
        x + ((size_t)bc * HH + 2u * oh) * WW) + 2u * ow4;
    float4 r0a = __ldcs(xr);
    float4 r0b = __ldcs(xr + 1);
    float4 r1a = __ldcs(xr + WW / 4);
    float4 r1b = __ldcs(xr + WW / 4 + 1);

    int row0 = 2 * (int)oh;
    int col0 = 8 * (int)ow4;     // global input col of first window

    float v0, ph0, pw0, v1, ph1, pw1, v2, ph2, pw2, v3, ph3, pw3;
    win2x2(r0a.x, r0a.y, r1a.x, r1a.y, row0, col0,     v0, ph0, pw0);
    win2x2(r0a.z, r0a.w, r1a.z, r1a.w, row0, col0 + 2, v1, ph1, pw1);
    win2x2(r0b.x, r0b.y, r1b.x, r1b.y, row0, col0 + 4, v2, ph2, pw2);
    win2x2(r0b.z, r0b.w, r1b.z, r1b.w, row0, col0 + 6, v3, ph3, pw3);

    // output: [B, 3C, OH, OW]; b = bc/128, c = bc%128
    unsigned b = bc >> 7;
    unsigned c = bc & 127u;
    float* o = out + (((size_t)b * 3u * CC + c) * OH + oh) * OW + 4u * ow4;

    __stcs(reinterpret_cast<float4*>(o),             make_float4(v0,  v1,  v2,  v3));
    __stcs(reinterpret_cast<float4*>(o + PLANE),     make_float4(ph0, ph1, ph2, ph3));
    __stcs(reinterpret_cast<float4*>(o + 2 * PLANE), make_float4(pw0, pw1, pw2, pw3));
}

extern "C" void kernel_launch(void* const* d_in, const int* in_sizes, int n_in,
                              void* d_out, int out_size) {
    const float* x = (const float*)d_in[0];
    float* out = (float*)d_out;
    // 4,194,304 threads total
    const unsigned nthreads = BB * CC * OH * (OW / 4);
    const unsigned block = 256;
    pap_pool_kernel<<<nthreads / block, block>>>(x, out);
}